// round 1
// baseline (speedup 1.0000x reference)
#include <cuda_runtime.h>
#include <math.h>

// SetConv2dEncoder: out[b,k,i,j] = sum_n w[b,n,i] * zc[b,n,k] * w[b,n,j]
// with w = exp(-0.5*(xz-x)^2/s2). Using the Gaussian product identity:
//   w_ni * w_nj = exp(-(x_i-x_j)^2/(4 s2)) * exp(-(p-u_n)^2/s2),  p=(x_i+x_j)/2
// and a uniform grid (p depends only on s=i+j), the einsum factorizes into a
// tiny midpoint table G[b,k,s] followed by a pure output-streaming kernel.
//
// Shapes (this problem): b=4, n=1024, c=16, m=1024. Output channels:
//   ch0 = identity(m), ch1 = density = C*G0, ch2..17 = C*Gk / (density+1e-8)

#define S_PAD 2048
#define NCH   17            // 1 (ones column) + c
#define EPS_DEN 1e-8f

__device__ float g_G[4 * NCH * S_PAD];   // midpoint table scratch (557 KB)

// ---------------------------------------------------------------------------
// Kernel A: G[b,k,s] = sum_n zc[b,n,k] * exp(-(p_s - xz[b,n])^2 / s2)
// One warp per (b, s). Lanes split n, warp-reduce 17 accumulators.
// ---------------------------------------------------------------------------
__global__ void __launch_bounds__(128) kernel_G(
    const float* __restrict__ xz, const float* __restrict__ z,
    const float* __restrict__ x_grid, const float* __restrict__ log_scale,
    int n, int m)
{
    const int S    = 2 * m - 1;
    const int warp = threadIdx.x >> 5;
    const int lane = threadIdx.x & 31;
    const int s    = blockIdx.x * 4 + warp;
    const int bb   = blockIdx.y;
    if (s >= S) return;

    const float inv_s2 = 1.0f / expf(2.0f * log_scale[0]);
    const int   s0 = s >> 1;
    const float p  = 0.5f * (x_grid[s0] + x_grid[s - s0]);

    float acc[NCH];
#pragma unroll
    for (int k = 0; k < NCH; k++) acc[k] = 0.0f;

    const float* __restrict__ xzb = xz + (size_t)bb * n;
    const float* __restrict__ zb  = z  + (size_t)bb * n * 16;

    for (int nn = lane; nn < n; nn += 32) {
        float d = p - xzb[nn];
        float e = expf(-d * d * inv_s2);
        // Gaussian is ~6% occupied: skip the FMA block when the whole warp
        // chunk underflowed (uniform branch via ballot).
        if (__ballot_sync(0xffffffffu, e != 0.0f)) {
            acc[0] += e;
            const float4* zr = (const float4*)(zb + (size_t)nn * 16);
            float4 z0 = zr[0], z1 = zr[1], z2 = zr[2], z3 = zr[3];
            acc[1]  += e * z0.x; acc[2]  += e * z0.y; acc[3]  += e * z0.z; acc[4]  += e * z0.w;
            acc[5]  += e * z1.x; acc[6]  += e * z1.y; acc[7]  += e * z1.z; acc[8]  += e * z1.w;
            acc[9]  += e * z2.x; acc[10] += e * z2.y; acc[11] += e * z2.z; acc[12] += e * z2.w;
            acc[13] += e * z3.x; acc[14] += e * z3.y; acc[15] += e * z3.z; acc[16] += e * z3.w;
        }
    }

#pragma unroll
    for (int off = 16; off; off >>= 1) {
#pragma unroll
        for (int k = 0; k < NCH; k++)
            acc[k] += __shfl_xor_sync(0xffffffffu, acc[k], off);
    }

    if (lane == 0) {
        float* Gb = g_G + (size_t)bb * NCH * S_PAD;
#pragma unroll
        for (int k = 0; k < NCH; k++) Gb[k * S_PAD + s] = acc[k];
    }
}

// ---------------------------------------------------------------------------
// Kernel B: stream the (b, 18, m, m) output. One block per (b, i) row;
// thread t owns j = 4t..4t+3 and emits one float4 per channel (18 STG.128).
// G reads are warp-coalesced scalars that live in L1/L2 (table is 557 KB).
// ---------------------------------------------------------------------------
__global__ void __launch_bounds__(256) kernel_out(
    const float* __restrict__ x_grid, const float* __restrict__ log_scale,
    float* __restrict__ out, int m)
{
    const int i  = blockIdx.x;
    const int bb = blockIdx.y;
    const int t  = threadIdx.x;
    const int j0 = t << 2;

    const float  xi = x_grid[i];
    const float4 xj = ((const float4*)x_grid)[t];
    const float  inv4s2 = 0.25f / expf(2.0f * log_scale[0]);

    float dx, c0, c1, c2, c3;
    dx = xi - xj.x; c0 = expf(-dx * dx * inv4s2);
    dx = xi - xj.y; c1 = expf(-dx * dx * inv4s2);
    dx = xi - xj.z; c2 = expf(-dx * dx * inv4s2);
    dx = xi - xj.w; c3 = expf(-dx * dx * inv4s2);

    const float* __restrict__ Gb = g_G + (size_t)bb * NCH * S_PAD;
    const int sb = i + j0;

    const size_t chstride = (size_t)m * m;
    float* op = out + ((size_t)bb * 18 * m + i) * m + j0;

    float4 v;
    // channel 0: identity
    v.x = (j0     == i) ? 1.0f : 0.0f;
    v.y = (j0 + 1 == i) ? 1.0f : 0.0f;
    v.z = (j0 + 2 == i) ? 1.0f : 0.0f;
    v.w = (j0 + 3 == i) ? 1.0f : 0.0f;
    *(float4*)op = v;

    // channel 1: density = C * G0
    float d0 = c0 * Gb[sb];
    float d1 = c1 * Gb[sb + 1];
    float d2 = c2 * Gb[sb + 2];
    float d3 = c3 * Gb[sb + 3];
    v.x = d0; v.y = d1; v.z = d2; v.w = d3;
    *(float4*)(op + chstride) = v;

    // channels 2..17: C*Gk / (density + eps) = Gk * (C / (density + eps))
    float r0 = c0 / (d0 + EPS_DEN);
    float r1 = c1 / (d1 + EPS_DEN);
    float r2 = c2 / (d2 + EPS_DEN);
    float r3 = c3 / (d3 + EPS_DEN);

#pragma unroll
    for (int k = 1; k < NCH; k++) {
        const float* __restrict__ Gk = Gb + k * S_PAD;
        v.x = Gk[sb]     * r0;
        v.y = Gk[sb + 1] * r1;
        v.z = Gk[sb + 2] * r2;
        v.w = Gk[sb + 3] * r3;
        *(float4*)(op + (size_t)(k + 1) * chstride) = v;
    }
}

// ---------------------------------------------------------------------------
extern "C" void kernel_launch(void* const* d_in, const int* in_sizes, int n_in,
                              void* d_out, int out_size)
{
    const float* xz        = (const float*)d_in[0];
    const float* z         = (const float*)d_in[1];
    const float* x_grid    = (const float*)d_in[2];
    const float* log_scale = (const float*)d_in[3];

    const int m = in_sizes[2];
    const long long xz_sz = in_sizes[0];
    const long long z_sz  = in_sizes[1];
    const int c = (int)(z_sz / xz_sz);                       // 16
    const long long per_b = (long long)(c + 2) * m * m;      // 18*m*m
    const long long b     = (long long)out_size / per_b;     // 4
    const long long header = (long long)out_size - b * per_b; // x_grid copy (m) or 0
    const int n = (int)(xz_sz / b);

    float* outp = (float*)d_out;
    if (header > 0) {
        // reference returns (x_grid, out): the flattened output leads with x_grid
        cudaMemcpyAsync(outp, x_grid, (size_t)header * sizeof(float),
                        cudaMemcpyDeviceToDevice, 0);
        outp += header;
    }

    const int S = 2 * m - 1;
    dim3 gA((unsigned)((S + 3) / 4), (unsigned)b);
    kernel_G<<<gA, 128>>>(xz, z, x_grid, log_scale, n, m);

    dim3 gB((unsigned)m, (unsigned)b);
    kernel_out<<<gB, m / 4>>>(x_grid, log_scale, outp, m);
}

// round 2
// speedup vs baseline: 1.7759x; 1.7759x over previous
#include <cuda_runtime.h>
#include <math.h>

// SetConv2dEncoder via Gaussian product factorization:
//   out[b,k,i,j] = C(i,j) * G[b,k,i+j],  C = exp(-(xi-xj)^2/(4 s2)),
//   G[b,k,s]     = sum_n zc[b,n,k] * exp(-(p_s - u_n)^2 / s2),  p_s = (x_i+x_j)/2
// kernel_G builds the tiny midpoint table (4 rotated copies so kernel_out can
// use aligned float4 loads); kernel_out is a pure DRAM-write streamer.

#define S_PAD   2048
#define NCH     17            // 1 (ones column) + c
#define EPS_DEN 1e-8f

// 4 batches x 4 rotations x 17 ch x 2048: copy r holds G[s] at index s-r.
__device__ __align__(16) float g_G4[4 * 4 * NCH * S_PAD];

// ---------------------------------------------------------------------------
// Kernel A: one thread per s (lanes cover 32 consecutive s -> all z/xz loads
// are warp-uniform broadcasts, L1-resident). 4 n-quarters per block, smem
// reduction. Ballot early-exit: Gaussian support is ~17% of n.
// ---------------------------------------------------------------------------
__global__ void __launch_bounds__(256) kernel_G(
    const float* __restrict__ xz, const float* __restrict__ z,
    const float* __restrict__ x_grid, const float* __restrict__ log_scale,
    int n, int m)
{
    const int S  = 2 * m - 1;
    const int t  = threadIdx.x;
    const int sl = t & 63;            // s-lane within tile
    const int q  = t >> 6;            // n-quarter 0..3
    const int s  = blockIdx.x * 64 + sl;
    const int bb = blockIdx.y;
    const int se = (s < S) ? s : (S - 1);   // clamp for safe p compute

    const float s2     = __expf(2.0f * log_scale[0]);
    const float inv_s2 = 1.0f / s2;
    const float thresh = 80.0f * s2;        // exp(-80) ~ 1.8e-35: negligible
    const int   s0 = se >> 1;
    const float p  = 0.5f * (x_grid[s0] + x_grid[se - s0]);

    float acc[NCH];
#pragma unroll
    for (int k = 0; k < NCH; k++) acc[k] = 0.0f;

    const float* __restrict__ xzb = xz + (size_t)bb * n;
    const float* __restrict__ zb  = z  + (size_t)bb * n * 16;

    const int nq = n >> 2;
    const int n0 = q * nq;
#pragma unroll 2
    for (int nn = n0; nn < n0 + nq; nn++) {
        float u  = __ldg(xzb + nn);        // warp-uniform broadcast
        float d  = p - u;
        float d2 = d * d;
        if (__ballot_sync(0xffffffffu, d2 < thresh)) {
            float e = __expf(-d2 * inv_s2);
            const float4* zr = (const float4*)(zb + ((size_t)nn << 4));
            float4 z0 = zr[0], z1 = zr[1], z2 = zr[2], z3 = zr[3];
            acc[0]  += e;
            acc[1]  += e * z0.x; acc[2]  += e * z0.y; acc[3]  += e * z0.z; acc[4]  += e * z0.w;
            acc[5]  += e * z1.x; acc[6]  += e * z1.y; acc[7]  += e * z1.z; acc[8]  += e * z1.w;
            acc[9]  += e * z2.x; acc[10] += e * z2.y; acc[11] += e * z2.z; acc[12] += e * z2.w;
            acc[13] += e * z3.x; acc[14] += e * z3.y; acc[15] += e * z3.z; acc[16] += e * z3.w;
        }
    }

    __shared__ float red[4][64][NCH];
#pragma unroll
    for (int k = 0; k < NCH; k++) red[q][sl][k] = acc[k];
    __syncthreads();

    if (q == 0 && s < S) {
        float* Gb = g_G4 + (size_t)bb * 4 * NCH * S_PAD;
#pragma unroll
        for (int k = 0; k < NCH; k++) {
            float v = red[0][sl][k] + red[1][sl][k] + red[2][sl][k] + red[3][sl][k];
#pragma unroll
            for (int r = 0; r < 4; r++) {
                int x = s - r;
                if (x >= 0) Gb[(r * NCH + k) * S_PAD + x] = v;
            }
        }
    }
}

// ---------------------------------------------------------------------------
// Kernel B: stream the (b, 18, m, m) output. Block = (i, b); thread t owns
// j = 4t..4t+3. Rotation copy (i&3) makes every per-channel G read a single
// aligned LDG.128. Streaming stores (__stcs) keep L1/L2 for the G table.
// ---------------------------------------------------------------------------
__global__ void __launch_bounds__(256) kernel_out(
    const float* __restrict__ x_grid, const float* __restrict__ log_scale,
    float* __restrict__ out, int m)
{
    const int i  = blockIdx.x;
    const int bb = blockIdx.y;
    const int t  = threadIdx.x;
    const int j0 = t << 2;

    const float  xi = x_grid[i];
    const float4 xj = ((const float4*)x_grid)[t];
    const float  inv4s2 = 0.25f / __expf(2.0f * log_scale[0]);

    float dx, c0, c1, c2, c3;
    dx = xi - xj.x; c0 = __expf(-dx * dx * inv4s2);
    dx = xi - xj.y; c1 = __expf(-dx * dx * inv4s2);
    dx = xi - xj.z; c2 = __expf(-dx * dx * inv4s2);
    dx = xi - xj.w; c3 = __expf(-dx * dx * inv4s2);

    const int ri = i & 3;
    const float* __restrict__ Gr =
        g_G4 + ((size_t)(bb * 4 + ri) * NCH) * S_PAD + (i - ri);

    const size_t chstride = (size_t)m * m;
    float* op = out + ((size_t)bb * 18 * m + i) * m + j0;

    float4 v;
    // channel 0: identity
    v.x = (j0     == i) ? 1.0f : 0.0f;
    v.y = (j0 + 1 == i) ? 1.0f : 0.0f;
    v.z = (j0 + 2 == i) ? 1.0f : 0.0f;
    v.w = (j0 + 3 == i) ? 1.0f : 0.0f;
    __stcs((float4*)op, v);

    // channel 1: density = C * G0  (single aligned float4 load)
    const float4 g0 = __ldg((const float4*)(Gr + j0));
    float d0 = c0 * g0.x, d1 = c1 * g0.y, d2 = c2 * g0.z, d3 = c3 * g0.w;
    v.x = d0; v.y = d1; v.z = d2; v.w = d3;
    __stcs((float4*)(op + chstride), v);

    // channels 2..17: Gk * (C / (density + eps))
    float r0 = c0 / (d0 + EPS_DEN);
    float r1 = c1 / (d1 + EPS_DEN);
    float r2 = c2 / (d2 + EPS_DEN);
    float r3 = c3 / (d3 + EPS_DEN);

#pragma unroll
    for (int k = 1; k < NCH; k++) {
        const float4 gk = __ldg((const float4*)(Gr + k * S_PAD + j0));
        v.x = gk.x * r0;
        v.y = gk.y * r1;
        v.z = gk.z * r2;
        v.w = gk.w * r3;
        __stcs((float4*)(op + (size_t)(k + 1) * chstride), v);
    }
}

// ---------------------------------------------------------------------------
extern "C" void kernel_launch(void* const* d_in, const int* in_sizes, int n_in,
                              void* d_out, int out_size)
{
    const float* xz        = (const float*)d_in[0];
    const float* z         = (const float*)d_in[1];
    const float* x_grid    = (const float*)d_in[2];
    const float* log_scale = (const float*)d_in[3];

    const int m = in_sizes[2];
    const long long xz_sz = in_sizes[0];
    const long long z_sz  = in_sizes[1];
    const int c = (int)(z_sz / xz_sz);                        // 16
    const long long per_b = (long long)(c + 2) * m * m;       // 18*m*m
    const long long b     = (long long)out_size / per_b;      // 4
    const long long header = (long long)out_size - b * per_b; // leading x_grid
    const int n = (int)(xz_sz / b);

    float* outp = (float*)d_out;
    if (header > 0) {
        cudaMemcpyAsync(outp, x_grid, (size_t)header * sizeof(float),
                        cudaMemcpyDeviceToDevice, 0);
        outp += header;
    }

    const int S = 2 * m - 1;
    dim3 gA((unsigned)((S + 63) / 64), (unsigned)b);
    kernel_G<<<gA, 256>>>(xz, z, x_grid, log_scale, n, m);

    dim3 gB((unsigned)m, (unsigned)b);
    kernel_out<<<gB, m / 4>>>(x_grid, log_scale, outp, m);
}